// round 16
// baseline (speedup 1.0000x reference)
#include <cuda_runtime.h>
#include <cuda_bf16.h>
#include <math.h>
#include <stdint.h>

// Problem constants
#define BB   2
#define SS   2048
#define DMODEL 2048
#define NH   16
#define DH   128
#define MTOT (BB*SS)

// ---------------------------------------------------------------------------
// Scratch (__device__ globals; allocation-free rule)
// ---------------------------------------------------------------------------
__device__ __nv_bfloat16 g_xh[(size_t)MTOT*DMODEL], g_xl[(size_t)MTOT*DMODEL];
__device__ __nv_bfloat16 g_wqh[(size_t)DMODEL*DMODEL], g_wql[(size_t)DMODEL*DMODEL];
__device__ __nv_bfloat16 g_wkh[(size_t)DMODEL*DMODEL], g_wkl[(size_t)DMODEL*DMODEL];
__device__ __nv_bfloat16 g_wvh[(size_t)DMODEL*DMODEL], g_wvl[(size_t)DMODEL*DMODEL];
__device__ __nv_bfloat16 g_wdh[(size_t)DMODEL*DMODEL], g_wdl[(size_t)DMODEL*DMODEL];
__device__ __nv_bfloat16 g_Qh[(size_t)BB*NH*SS*DH], g_Ql[(size_t)BB*NH*SS*DH];
__device__ __nv_bfloat16 g_Kh[(size_t)BB*NH*SS*DH], g_Kl[(size_t)BB*NH*SS*DH];
__device__ __nv_bfloat16 g_Vh[(size_t)BB*NH*SS*DH], g_Vl[(size_t)BB*NH*SS*DH];
__device__ __nv_bfloat16 g_Oh[(size_t)BB*SS*DMODEL], g_Ol[(size_t)BB*SS*DMODEL];

// ---------------------------------------------------------------------------
// PTX helpers (legacy mma.sync — tcgen05 rejected by this toolchain)
// ---------------------------------------------------------------------------
__device__ __forceinline__ unsigned smem_u32(const void* p) {
    return (unsigned)__cvta_generic_to_shared(p);
}
__device__ __forceinline__ void ldsm4(unsigned* r, unsigned addr) {
    asm volatile("ldmatrix.sync.aligned.m8n8.x4.shared.b16 {%0,%1,%2,%3}, [%4];\n"
        : "=r"(r[0]), "=r"(r[1]), "=r"(r[2]), "=r"(r[3]) : "r"(addr));
}
__device__ __forceinline__ void mma16816(float* c, const unsigned* a,
                                         unsigned b0, unsigned b1) {
    asm volatile(
        "mma.sync.aligned.m16n8k16.row.col.f32.bf16.bf16.f32 "
        "{%0,%1,%2,%3}, {%4,%5,%6,%7}, {%8,%9}, {%0,%1,%2,%3};\n"
        : "+f"(c[0]), "+f"(c[1]), "+f"(c[2]), "+f"(c[3])
        : "r"(a[0]), "r"(a[1]), "r"(a[2]), "r"(a[3]), "r"(b0), "r"(b1));
}
__device__ __forceinline__ unsigned packbf2(float x, float y) {
    __nv_bfloat162 t = __floats2bfloat162_rn(x, y);
    return *(unsigned*)&t;
}
__device__ __forceinline__ void cpa16(unsigned dst, const void* src) {
    asm volatile("cp.async.cg.shared.global [%0], [%1], 16;\n" :: "r"(dst), "l"(src));
}
#define CPA_COMMIT() asm volatile("cp.async.commit_group;\n" ::: "memory")
#define CPA_WAIT0()  asm volatile("cp.async.wait_group 0;\n" ::: "memory")
#define CPA_WAIT1()  asm volatile("cp.async.wait_group 1;\n" ::: "memory")
#define CPA_WAIT2()  asm volatile("cp.async.wait_group 2;\n" ::: "memory")

// RoPE factor (reference's rotate_half == identity):
// fac(s,d) = cos(s*inv_freq[d&63]) + sin(s*inv_freq[d&63])
__device__ __forceinline__ float rope_fac(int s, int d) {
    int j = d & 63;
    float inv = expf(-(float)(2*j) * (9.210340371976184f / 128.0f));
    float f = (float)s * inv;
    float sn, cs;
    sincosf(f, &sn, &cs);
    return cs + sn;
}

// ---------------------------------------------------------------------------
// Split fp32 -> bf16 hi/lo : single fused launch.
// blockIdx.y: 0,1 -> x halves; 2..5 -> Wq,Wk,Wv,Wd
// ---------------------------------------------------------------------------
__global__ void split6_kernel(const float4* __restrict__ x,
                              const float4* __restrict__ wq, const float4* __restrict__ wk,
                              const float4* __restrict__ wv, const float4* __restrict__ wd,
                              uint2* __restrict__ xh, uint2* __restrict__ xl,
                              uint2* __restrict__ qh, uint2* __restrict__ ql,
                              uint2* __restrict__ kh, uint2* __restrict__ kl,
                              uint2* __restrict__ vh, uint2* __restrict__ vl,
                              uint2* __restrict__ dh, uint2* __restrict__ dl)
{
    const int WN4 = DMODEL * DMODEL / 4;
    int y = blockIdx.y;
    int i = blockIdx.x * blockDim.x + threadIdx.x;
    const float4* src; uint2 *hi, *lo;
    if (y == 0)      { src = x;              hi = xh;       lo = xl; }
    else if (y == 1) { src = x + WN4;        hi = xh + WN4; lo = xl + WN4; }
    else if (y == 2) { src = wq; hi = qh; lo = ql; }
    else if (y == 3) { src = wk; hi = kh; lo = kl; }
    else if (y == 4) { src = wv; hi = vh; lo = vl; }
    else             { src = wd; hi = dh; lo = dl; }
    float4 v = src[i];
    __nv_bfloat162 h0 = __floats2bfloat162_rn(v.x, v.y);
    __nv_bfloat162 h1 = __floats2bfloat162_rn(v.z, v.w);
    hi[i] = make_uint2(*(unsigned*)&h0, *(unsigned*)&h1);
    __nv_bfloat162 l0 = __floats2bfloat162_rn(v.x - __bfloat162float(h0.x),
                                              v.y - __bfloat162float(h0.y));
    __nv_bfloat162 l1 = __floats2bfloat162_rn(v.z - __bfloat162float(h1.x),
                                              v.w - __bfloat162float(h1.y));
    lo[i] = make_uint2(*(unsigned*)&l0, *(unsigned*)&l1);
}

// ---------------------------------------------------------------------------
// GEMM (legacy HMMA, bf16 split-3, cp.async 4-stage pipeline)
//   C[m][n] = sum_k A[m][k]*B[n][k];  pre-split bf16 operands.
// 512 threads (16 warps = 4/SMSP), block tile 128x128x32,
// warp grid 4Mx4N (warp tile 32x32) -> acc 32 regs/thread, no spills
// at the natural 128-reg cap. 4 stages x 32KB smem, 1 CTA/SM.
// ---------------------------------------------------------------------------
#define STG_BYTES 32768
#define SA_AH 0
#define SA_AL 8192
#define SA_BH 16384
#define SA_BL 24576
#define TG_SMEM (4*STG_BYTES)    // 128KB

__device__ __forceinline__ unsigned swz_off(int r, int u) {
    return (unsigned)(r * 64 + ((u ^ ((r >> 1) & 3)) << 4));
}

__global__ __launch_bounds__(512, 1)
void gemm_tc2(const __nv_bfloat16* __restrict__ Ain_h, const __nv_bfloat16* __restrict__ Ain_l,
              const __nv_bfloat16* __restrict__ w0h, const __nv_bfloat16* __restrict__ w0l,
              const __nv_bfloat16* __restrict__ w1h, const __nv_bfloat16* __restrict__ w1l,
              const __nv_bfloat16* __restrict__ w2h, const __nv_bfloat16* __restrict__ w2l,
              __nv_bfloat16* __restrict__ d0h, __nv_bfloat16* __restrict__ d0l,
              __nv_bfloat16* __restrict__ d1h, __nv_bfloat16* __restrict__ d1l,
              __nv_bfloat16* __restrict__ d2h, __nv_bfloat16* __restrict__ d2l,
              float* __restrict__ Cout)
{
    extern __shared__ __align__(16) char smem[];
    const unsigned sb = smem_u32(smem);

    const int tid  = threadIdx.x;
    const int lane = tid & 31;
    const int wid  = tid >> 5;        // 0..15
    const int wm   = wid >> 2;        // 0..3 (32 M-rows each)
    const int wn   = wid & 3;         // 0..3 (32 N-cols each)
    const int g    = lane >> 2;
    const int tg   = lane & 3;
    const int bn   = blockIdx.x, bm = blockIdx.y, z = blockIdx.z;

    const __nv_bfloat16* Bh = (z == 0) ? w0h : (z == 1) ? w1h : w2h;
    const __nv_bfloat16* Bl = (z == 0) ? w0l : (z == 1) ? w1l : w2l;
    __nv_bfloat16* Dh = (z == 0) ? d0h : (z == 1) ? d1h : d2h;
    __nv_bfloat16* Dl = (z == 0) ? d0l : (z == 1) ? d1l : d2l;
    const int mode = Cout ? 0 : ((z <= 1) ? 2 : 1);

    const __nv_bfloat16* Ahg = Ain_h + (size_t)(bm * 128) * DMODEL;
    const __nv_bfloat16* Alg = Ain_l + (size_t)(bm * 128) * DMODEL;
    const __nv_bfloat16* Bhg = Bh + (size_t)(bn * 128) * DMODEL;
    const __nv_bfloat16* Blg = Bl + (size_t)(bn * 128) * DMODEL;
    const __nv_bfloat16* srcs[4] = {Ahg, Alg, Bhg, Blg};

    // staging: 4 arrays x (128 rows x 4 u-slots) = 2048 cp.async / 512 thr = 4 each
    const int r_st = tid >> 2;       // 0..127
    const int u_st = tid & 3;

    float acc[2][4][4];
#pragma unroll
    for (int mt = 0; mt < 2; mt++)
#pragma unroll
        for (int nt = 0; nt < 4; nt++)
#pragma unroll
            for (int e = 0; e < 4; e++) acc[mt][nt][e] = 0.f;

#define ISSUE_STAGE(S, BUF)                                                    \
    do {                                                                       \
        const int k0_ = (S) * 32;                                              \
        const unsigned stb_ = sb + (BUF) * STG_BYTES;                          \
        _Pragma("unroll")                                                      \
        for (int arr = 0; arr < 4; arr++) {                                    \
            cpa16(stb_ + arr * 8192 + swz_off(r_st, u_st),                     \
                  srcs[arr] + (size_t)r_st * DMODEL + k0_ + u_st * 8);         \
        }                                                                      \
    } while (0)

    ISSUE_STAGE(0, 0); CPA_COMMIT();
    ISSUE_STAGE(1, 1); CPA_COMMIT();
    ISSUE_STAGE(2, 2); CPA_COMMIT();

    const int NST = DMODEL / 32;   // 64
    for (int s = 0; s < NST; s++) {
        if (s < NST - 2)      CPA_WAIT2();
        else if (s == NST-2)  CPA_WAIT1();
        else                  CPA_WAIT0();
        __syncthreads();
        if (s + 3 < NST) { ISSUE_STAGE(s + 3, (s + 3) & 3); CPA_COMMIT(); }

        const unsigned stb = sb + (s & 3) * STG_BYTES;
#pragma unroll
        for (int ks = 0; ks < 2; ks++) {
            const int u = 2 * ks + (lane >> 4);
            const int ar_base = wm * 32 + (lane & 15);
            const int br_base = wn * 32 + (lane & 15);
            unsigned afr[2][4], bfr[2][4];
            // A-hi, B-hi
#pragma unroll
            for (int mt = 0; mt < 2; mt++)
                ldsm4(afr[mt], stb + SA_AH + swz_off(ar_base + mt * 16, u));
#pragma unroll
            for (int bt = 0; bt < 2; bt++)
                ldsm4(bfr[bt], stb + SA_BH + swz_off(br_base + bt * 16, u));
            // P1: hh
#pragma unroll
            for (int mt = 0; mt < 2; mt++)
#pragma unroll
                for (int nt = 0; nt < 4; nt++)
                    mma16816(acc[mt][nt], afr[mt],
                             bfr[nt >> 1][nt & 1], bfr[nt >> 1][(nt & 1) + 2]);
            // B-lo; P2: h*l
#pragma unroll
            for (int bt = 0; bt < 2; bt++)
                ldsm4(bfr[bt], stb + SA_BL + swz_off(br_base + bt * 16, u));
#pragma unroll
            for (int mt = 0; mt < 2; mt++)
#pragma unroll
                for (int nt = 0; nt < 4; nt++)
                    mma16816(acc[mt][nt], afr[mt],
                             bfr[nt >> 1][nt & 1], bfr[nt >> 1][(nt & 1) + 2]);
            // A-lo, reload B-hi; P3: l*h
#pragma unroll
            for (int mt = 0; mt < 2; mt++)
                ldsm4(afr[mt], stb + SA_AL + swz_off(ar_base + mt * 16, u));
#pragma unroll
            for (int bt = 0; bt < 2; bt++)
                ldsm4(bfr[bt], stb + SA_BH + swz_off(br_base + bt * 16, u));
#pragma unroll
            for (int mt = 0; mt < 2; mt++)
#pragma unroll
                for (int nt = 0; nt < 4; nt++)
                    mma16816(acc[mt][nt], afr[mt],
                             bfr[nt >> 1][nt & 1], bfr[nt >> 1][(nt & 1) + 2]);
        }
    }
#undef ISSUE_STAGE

    // ---- epilogue ----
#pragma unroll
    for (int mt = 0; mt < 2; mt++) {
#pragma unroll
        for (int nt = 0; nt < 4; nt++) {
            int m0  = bm * 128 + wm * 32 + mt * 16 + g;
            int col = wn * 32 + nt * 8 + tg * 2;      // 0..127 within block
            float v00 = acc[mt][nt][0], v01 = acc[mt][nt][1];
            float v10 = acc[mt][nt][2], v11 = acc[mt][nt][3];
            if (mode == 0) {
                *(float2*)(Cout + (size_t)m0 * DMODEL + bn * 128 + col) = make_float2(v00, v01);
                *(float2*)(Cout + (size_t)(m0 + 8) * DMODEL + bn * 128 + col) = make_float2(v10, v11);
            } else {
                int b0 = m0 >> 11, s0 = m0 & 2047;
                int m1 = m0 + 8;
                int b1 = m1 >> 11, s1 = m1 & 2047;
                if (mode == 2) {
                    v00 *= rope_fac(s0, col); v01 *= rope_fac(s0, col + 1);
                    v10 *= rope_fac(s1, col); v11 *= rope_fac(s1, col + 1);
                }
                size_t i0 = ((size_t)(b0 * NH + bn) * SS + s0) * DH + col;
                size_t i1 = ((size_t)(b1 * NH + bn) * SS + s1) * DH + col;
                __nv_bfloat162 hb;
                hb = __floats2bfloat162_rn(v00, v01);
                *(unsigned*)(Dh + i0) = *(unsigned*)&hb;
                *(unsigned*)(Dl + i0) = packbf2(v00 - __bfloat162float(hb.x),
                                                v01 - __bfloat162float(hb.y));
                hb = __floats2bfloat162_rn(v10, v11);
                *(unsigned*)(Dh + i1) = *(unsigned*)&hb;
                *(unsigned*)(Dl + i1) = packbf2(v10 - __bfloat162float(hb.x),
                                                v11 - __bfloat162float(hb.y));
            }
        }
    }
}

// ---------------------------------------------------------------------------
// Tensor-core causal flash attention (round-10 version, known 518us).
// ---------------------------------------------------------------------------
#define AQH 0
#define AQL 32768
#define AKH 65536
#define AKL 81920
#define AVH 98304
#define AVL 114688
#define ATT_SMEM 131072

__global__ __launch_bounds__(256, 1)
void attn_mma_kernel(const __nv_bfloat16* __restrict__ Qh, const __nv_bfloat16* __restrict__ Ql,
                     const __nv_bfloat16* __restrict__ Kh, const __nv_bfloat16* __restrict__ Kl,
                     const __nv_bfloat16* __restrict__ Vh, const __nv_bfloat16* __restrict__ Vl,
                     __nv_bfloat16* __restrict__ Oh, __nv_bfloat16* __restrict__ Ol)
{
    extern __shared__ __align__(16) char smem[];
    const unsigned sbm = smem_u32(smem);

    const int tid  = threadIdx.x;
    const int lane = tid & 31;
    const int w    = tid >> 5;
    const int g    = lane >> 2;
    const int qd   = lane & 3;
    const int qt   = blockIdx.x;
    const int h    = blockIdx.y;
    const int b    = blockIdx.z;

    const size_t base = ((size_t)(b*NH + h)) * SS * DH;
    const __nv_bfloat16* Qhg = Qh + base + (size_t)qt * 128 * DH;
    const __nv_bfloat16* Qlg = Ql + base + (size_t)qt * 128 * DH;
    const __nv_bfloat16* Khg = Kh + base;
    const __nv_bfloat16* Klg = Kl + base;
    const __nv_bfloat16* Vhg = Vh + base;
    const __nv_bfloat16* Vlg = Vl + base;

#pragma unroll
    for (int rep = 0; rep < 8; rep++) {
        int idx = tid + rep * 256;
        int r = idx >> 4, u = idx & 15;
        unsigned off = (unsigned)(r * 256 + ((u ^ (r & 7)) << 4));
        *(uint4*)(smem + AQH + off) = *(const uint4*)(Qhg + (size_t)r * DH + u * 8);
        *(uint4*)(smem + AQL + off) = *(const uint4*)(Qlg + (size_t)r * DH + u * 8);
    }

    float o[16][4];
#pragma unroll
    for (int nj = 0; nj < 16; nj++)
#pragma unroll
        for (int e = 0; e < 4; e++) o[nj][e] = 0.f;
    float mrow[2] = {-INFINITY, -INFINITY};
    float lrow[2] = {0.f, 0.f};

    const float scale = 0.08838834764831845f;
    const int ktmax = 2 * qt + 1;

    for (int kt = 0; kt <= ktmax; kt++) {
        __syncthreads();
#pragma unroll
        for (int rep = 0; rep < 4; rep++) {
            int idx = tid + rep * 256;
            int r = idx >> 4, u = idx & 15;
            unsigned off = (unsigned)(r * 256 + ((u ^ (r & 7)) << 4));
            *(uint4*)(smem + AKH + off) = *(const uint4*)(Khg + (size_t)(kt*64 + r) * DH + u * 8);
            *(uint4*)(smem + AKL + off) = *(const uint4*)(Klg + (size_t)(kt*64 + r) * DH + u * 8);
        }
#pragma unroll
        for (int rep = 0; rep < 4; rep++) {
            int idx = tid + rep * 256;
            int kk = idx & 63, u = idx >> 6;
            uint4 hv = *(const uint4*)(Vhg + (size_t)(kt*64 + kk) * DH + u * 8);
            uint4 lv = *(const uint4*)(Vlg + (size_t)(kt*64 + kk) * DH + u * 8);
            const unsigned short* hs = (const unsigned short*)&hv;
            const unsigned short* ls = (const unsigned short*)&lv;
#pragma unroll
            for (int dd = 0; dd < 8; dd++) {
                int d = u * 8 + dd;
                unsigned off = (unsigned)(d * 128 + (((kk >> 3) ^ (d & 7)) << 4) + ((kk & 7) << 1));
                *(unsigned short*)(smem + AVH + off) = hs[dd];
                *(unsigned short*)(smem + AVL + off) = ls[dd];
            }
        }
        __syncthreads();

        float s[8][4];
#pragma unroll
        for (int nj = 0; nj < 8; nj++)
#pragma unroll
            for (int e = 0; e < 4; e++) s[nj][e] = 0.f;

#pragma unroll
        for (int ks = 0; ks < 8; ks++) {
            unsigned ah[4], al[4];
            {
                int row = w * 16 + (lane & 15);
                int u = 2 * ks + (lane >> 4);
                unsigned off = (unsigned)(row * 256 + ((u ^ (row & 7)) << 4));
                ldsm4(ah, sbm + AQH + off);
                ldsm4(al, sbm + AQL + off);
            }
#pragma unroll
            for (int g4 = 0; g4 < 4; g4++) {
                unsigned bh[4], bl[4];
                int row = g4 * 16 + (lane & 15);
                int u = 2 * ks + (lane >> 4);
                unsigned off = (unsigned)(row * 256 + ((u ^ (row & 7)) << 4));
                ldsm4(bh, sbm + AKH + off);
                ldsm4(bl, sbm + AKL + off);
#pragma unroll
                for (int jj = 0; jj < 2; jj++) {
                    int nj = 2 * g4 + jj;
                    mma16816(s[nj], ah, bh[jj], bh[jj + 2]);
                    mma16816(s[nj], ah, bl[jj], bl[jj + 2]);
                    mma16816(s[nj], al, bh[jj], bh[jj + 2]);
                }
            }
        }

        const int r0 = qt * 128 + w * 16 + g;
        const int r1 = r0 + 8;
        const bool tail = (kt >= 2 * qt);
#pragma unroll
        for (int nj = 0; nj < 8; nj++) {
            int c0 = kt * 64 + nj * 8 + qd * 2;
#pragma unroll
            for (int e = 0; e < 4; e++) {
                s[nj][e] *= scale;
                if (tail) {
                    int col = c0 + (e & 1);
                    int row = (e < 2) ? r0 : r1;
                    if (col > row) s[nj][e] = -INFINITY;
                }
            }
        }

        float alpha[2];
#pragma unroll
        for (int half = 0; half < 2; half++) {
            float mx = -INFINITY;
#pragma unroll
            for (int nj = 0; nj < 8; nj++)
                mx = fmaxf(mx, fmaxf(s[nj][2*half], s[nj][2*half+1]));
            mx = fmaxf(mx, __shfl_xor_sync(0xffffffffu, mx, 1));
            mx = fmaxf(mx, __shfl_xor_sync(0xffffffffu, mx, 2));
            float newm = fmaxf(mrow[half], mx);
            float sum = 0.f;
#pragma unroll
            for (int nj = 0; nj < 8; nj++) {
                float p0 = __expf(s[nj][2*half]   - newm);
                float p1 = __expf(s[nj][2*half+1] - newm);
                s[nj][2*half]   = p0;
                s[nj][2*half+1] = p1;
                sum += p0 + p1;
            }
            sum += __shfl_xor_sync(0xffffffffu, sum, 1);
            sum += __shfl_xor_sync(0xffffffffu, sum, 2);
            alpha[half] = __expf(mrow[half] - newm);
            lrow[half] = lrow[half] * alpha[half] + sum;
            mrow[half] = newm;
        }
#pragma unroll
        for (int nj = 0; nj < 16; nj++) {
            o[nj][0] *= alpha[0]; o[nj][1] *= alpha[0];
            o[nj][2] *= alpha[1]; o[nj][3] *= alpha[1];
        }

#pragma unroll
        for (int tpv = 0; tpv < 4; tpv++) {
            unsigned pah[4], pal[4];
            {
                float p00 = s[2*tpv][0],   p01 = s[2*tpv][1];
                float p02 = s[2*tpv][2],   p03 = s[2*tpv][3];
                float p10 = s[2*tpv+1][0], p11 = s[2*tpv+1][1];
                float p12 = s[2*tpv+1][2], p13 = s[2*tpv+1][3];
                __nv_bfloat162 hb;
                hb = __floats2bfloat162_rn(p00, p01); pah[0] = *(unsigned*)&hb;
                pal[0] = packbf2(p00 - __bfloat162float(hb.x), p01 - __bfloat162float(hb.y));
                hb = __floats2bfloat162_rn(p02, p03); pah[1] = *(unsigned*)&hb;
                pal[1] = packbf2(p02 - __bfloat162float(hb.x), p03 - __bfloat162float(hb.y));
                hb = __floats2bfloat162_rn(p10, p11); pah[2] = *(unsigned*)&hb;
                pal[2] = packbf2(p10 - __bfloat162float(hb.x), p11 - __bfloat162float(hb.y));
                hb = __floats2bfloat162_rn(p12, p13); pah[3] = *(unsigned*)&hb;
                pal[3] = packbf2(p12 - __bfloat162float(hb.x), p13 - __bfloat162float(hb.y));
            }
#pragma unroll
            for (int g4 = 0; g4 < 8; g4++) {
                unsigned vbh[4], vbl[4];
                int row = g4 * 16 + (lane & 15);
                int u = 2 * tpv + (lane >> 4);
                unsigned off = (unsigned)(row * 128 + ((u ^ (row & 7)) << 4));
                ldsm4(vbh, sbm + AVH + off);
                ldsm4(vbl, sbm + AVL + off);
#pragma unroll
                for (int jj = 0; jj < 2; jj++) {
                    int njo = 2 * g4 + jj;
                    mma16816(o[njo], pah, vbh[jj], vbh[jj + 2]);
                    mma16816(o[njo], pah, vbl[jj], vbl[jj + 2]);
                    mma16816(o[njo], pal, vbh[jj], vbh[jj + 2]);
                }
            }
        }
    }

    const float inv0 = 1.f / lrow[0];
    const float inv1 = 1.f / lrow[1];
    const int r0 = qt * 128 + w * 16 + g;
    const int r1 = r0 + 8;
    __nv_bfloat16* Ohg = Oh + (size_t)b * SS * DMODEL + (size_t)h * DH;
    __nv_bfloat16* Olg = Ol + (size_t)b * SS * DMODEL + (size_t)h * DH;
#pragma unroll
    for (int njo = 0; njo < 16; njo++) {
        int col = njo * 8 + qd * 2;
        float v0 = o[njo][0] * inv0, v1 = o[njo][1] * inv0;
        float v2 = o[njo][2] * inv1, v3 = o[njo][3] * inv1;
        __nv_bfloat162 hb;
        hb = __floats2bfloat162_rn(v0, v1);
        *(unsigned*)(Ohg + (size_t)r0 * DMODEL + col) = *(unsigned*)&hb;
        *(unsigned*)(Olg + (size_t)r0 * DMODEL + col) =
            packbf2(v0 - __bfloat162float(hb.x), v1 - __bfloat162float(hb.y));
        hb = __floats2bfloat162_rn(v2, v3);
        *(unsigned*)(Ohg + (size_t)r1 * DMODEL + col) = *(unsigned*)&hb;
        *(unsigned*)(Olg + (size_t)r1 * DMODEL + col) =
            packbf2(v2 - __bfloat162float(hb.x), v3 - __bfloat162float(hb.y));
    }
}

// ---------------------------------------------------------------------------
// Launch
// ---------------------------------------------------------------------------
extern "C" void kernel_launch(void* const* d_in, const int* in_sizes, int n_in,
                              void* d_out, int out_size)
{
    (void)out_size;
    const int X_ELEMS = MTOT * DMODEL;

    const float *x, *Wq, *Wk, *Wv, *Wd;
    if (n_in >= 6 && in_sizes[0] == X_ELEMS) {
        x  = (const float*)d_in[0];
        Wq = (const float*)d_in[2];
        Wk = (const float*)d_in[3];
        Wv = (const float*)d_in[4];
        Wd = (const float*)d_in[5];
    } else {
        Wd = (const float*)d_in[0];
        Wk = (const float*)d_in[1];
        Wq = (const float*)d_in[2];
        Wv = (const float*)d_in[3];
        x  = (const float*)d_in[5];
    }
    float* out = (float*)d_out;

    __nv_bfloat16 *xh,*xl,*wqh,*wql,*wkh,*wkl,*wvh,*wvl,*wdh,*wdl;
    __nv_bfloat16 *Qh,*Ql,*Kh,*Kl,*Vh,*Vl,*Oh,*Ol;
    cudaGetSymbolAddress((void**)&xh,  g_xh);  cudaGetSymbolAddress((void**)&xl,  g_xl);
    cudaGetSymbolAddress((void**)&wqh, g_wqh); cudaGetSymbolAddress((void**)&wql, g_wql);
    cudaGetSymbolAddress((void**)&wkh, g_wkh); cudaGetSymbolAddress((void**)&wkl, g_wkl);
    cudaGetSymbolAddress((void**)&wvh, g_wvh); cudaGetSymbolAddress((void**)&wvl, g_wvl);
    cudaGetSymbolAddress((void**)&wdh, g_wdh); cudaGetSymbolAddress((void**)&wdl, g_wdl);
    cudaGetSymbolAddress((void**)&Qh,  g_Qh);  cudaGetSymbolAddress((void**)&Ql,  g_Ql);
    cudaGetSymbolAddress((void**)&Kh,  g_Kh);  cudaGetSymbolAddress((void**)&Kl,  g_Kl);
    cudaGetSymbolAddress((void**)&Vh,  g_Vh);  cudaGetSymbolAddress((void**)&Vl,  g_Vl);
    cudaGetSymbolAddress((void**)&Oh,  g_Oh);  cudaGetSymbolAddress((void**)&Ol,  g_Ol);

    const int WN4 = DMODEL * DMODEL / 4;
    split6_kernel<<<dim3(WN4/256, 6), 256>>>(
        (const float4*)x, (const float4*)Wq, (const float4*)Wk,
        (const float4*)Wv, (const float4*)Wd,
        (uint2*)xh, (uint2*)xl, (uint2*)wqh, (uint2*)wql,
        (uint2*)wkh, (uint2*)wkl, (uint2*)wvh, (uint2*)wvl,
        (uint2*)wdh, (uint2*)wdl);

    cudaFuncSetAttribute(gemm_tc2,
                         cudaFuncAttributeMaxDynamicSharedMemorySize, TG_SMEM);
    cudaFuncSetAttribute(attn_mma_kernel,
                         cudaFuncAttributeMaxDynamicSharedMemorySize, ATT_SMEM);

    // fused Q/K/V projection (+RoPE on Q,K)
    gemm_tc2<<<dim3(DMODEL/128, MTOT/128, 3), 512, TG_SMEM>>>(
        xh, xl,
        wqh, wql, wkh, wkl, wvh, wvl,
        Qh, Ql, Kh, Kl, Vh, Vl,
        nullptr);

    attn_mma_kernel<<<dim3(SS/128, NH, BB), 256, ATT_SMEM>>>(Qh, Ql, Kh, Kl, Vh, Vl, Oh, Ol);

    // output projection -> fp32 out
    gemm_tc2<<<dim3(DMODEL/128, MTOT/128, 1), 512, TG_SMEM>>>(
        Oh, Ol,
        wdh, wdl, wdh, wdl, wdh, wdl,
        nullptr, nullptr, nullptr, nullptr, nullptr, nullptr,
        out);
}

// round 17
// speedup vs baseline: 1.7018x; 1.7018x over previous
#include <cuda_runtime.h>
#include <cuda_bf16.h>
#include <math.h>
#include <stdint.h>

// Problem constants
#define BB   2
#define SS   2048
#define DMODEL 2048
#define NH   16
#define DH   128
#define MTOT (BB*SS)

// ---------------------------------------------------------------------------
// Scratch (__device__ globals; allocation-free rule)
// ---------------------------------------------------------------------------
__device__ __nv_bfloat16 g_xh[(size_t)MTOT*DMODEL], g_xl[(size_t)MTOT*DMODEL];
__device__ __nv_bfloat16 g_wqh[(size_t)DMODEL*DMODEL], g_wql[(size_t)DMODEL*DMODEL];
__device__ __nv_bfloat16 g_wkh[(size_t)DMODEL*DMODEL], g_wkl[(size_t)DMODEL*DMODEL];
__device__ __nv_bfloat16 g_wvh[(size_t)DMODEL*DMODEL], g_wvl[(size_t)DMODEL*DMODEL];
__device__ __nv_bfloat16 g_wdh[(size_t)DMODEL*DMODEL], g_wdl[(size_t)DMODEL*DMODEL];
__device__ __nv_bfloat16 g_Qh[(size_t)BB*NH*SS*DH], g_Ql[(size_t)BB*NH*SS*DH];
__device__ __nv_bfloat16 g_Kh[(size_t)BB*NH*SS*DH], g_Kl[(size_t)BB*NH*SS*DH];
__device__ __nv_bfloat16 g_Vh[(size_t)BB*NH*SS*DH], g_Vl[(size_t)BB*NH*SS*DH];
__device__ __nv_bfloat16 g_Oh[(size_t)BB*SS*DMODEL], g_Ol[(size_t)BB*SS*DMODEL];

// ---------------------------------------------------------------------------
// PTX helpers (legacy mma.sync — tcgen05 rejected by this toolchain)
// ---------------------------------------------------------------------------
__device__ __forceinline__ unsigned smem_u32(const void* p) {
    return (unsigned)__cvta_generic_to_shared(p);
}
__device__ __forceinline__ void ldsm4(unsigned* r, unsigned addr) {
    asm volatile("ldmatrix.sync.aligned.m8n8.x4.shared.b16 {%0,%1,%2,%3}, [%4];\n"
        : "=r"(r[0]), "=r"(r[1]), "=r"(r[2]), "=r"(r[3]) : "r"(addr));
}
__device__ __forceinline__ void mma16816(float* c, const unsigned* a,
                                         unsigned b0, unsigned b1) {
    asm volatile(
        "mma.sync.aligned.m16n8k16.row.col.f32.bf16.bf16.f32 "
        "{%0,%1,%2,%3}, {%4,%5,%6,%7}, {%8,%9}, {%0,%1,%2,%3};\n"
        : "+f"(c[0]), "+f"(c[1]), "+f"(c[2]), "+f"(c[3])
        : "r"(a[0]), "r"(a[1]), "r"(a[2]), "r"(a[3]), "r"(b0), "r"(b1));
}
__device__ __forceinline__ unsigned packbf2(float x, float y) {
    __nv_bfloat162 t = __floats2bfloat162_rn(x, y);
    return *(unsigned*)&t;
}
__device__ __forceinline__ void cpa16(unsigned dst, const void* src) {
    asm volatile("cp.async.cg.shared.global [%0], [%1], 16;\n" :: "r"(dst), "l"(src));
}
#define CPA_COMMIT() asm volatile("cp.async.commit_group;\n" ::: "memory")
#define CPA_WAIT1()  asm volatile("cp.async.wait_group 1;\n" ::: "memory")

// RoPE factor (reference's rotate_half == identity):
// fac(s,d) = cos(s*inv_freq[d&63]) + sin(s*inv_freq[d&63])
__device__ __forceinline__ float rope_fac(int s, int d) {
    int j = d & 63;
    float inv = expf(-(float)(2*j) * (9.210340371976184f / 128.0f));
    float f = (float)s * inv;
    float sn, cs;
    sincosf(f, &sn, &cs);
    return cs + sn;
}

// ---------------------------------------------------------------------------
// Split fp32 -> bf16 hi/lo : single fused launch.
// ---------------------------------------------------------------------------
__global__ void split6_kernel(const float4* __restrict__ x,
                              const float4* __restrict__ wq, const float4* __restrict__ wk,
                              const float4* __restrict__ wv, const float4* __restrict__ wd,
                              uint2* __restrict__ xh, uint2* __restrict__ xl,
                              uint2* __restrict__ qh, uint2* __restrict__ ql,
                              uint2* __restrict__ kh, uint2* __restrict__ kl,
                              uint2* __restrict__ vh, uint2* __restrict__ vl,
                              uint2* __restrict__ dh, uint2* __restrict__ dl)
{
    const int WN4 = DMODEL * DMODEL / 4;
    int y = blockIdx.y;
    int i = blockIdx.x * blockDim.x + threadIdx.x;
    const float4* src; uint2 *hi, *lo;
    if (y == 0)      { src = x;              hi = xh;       lo = xl; }
    else if (y == 1) { src = x + WN4;        hi = xh + WN4; lo = xl + WN4; }
    else if (y == 2) { src = wq; hi = qh; lo = ql; }
    else if (y == 3) { src = wk; hi = kh; lo = kl; }
    else if (y == 4) { src = wv; hi = vh; lo = vl; }
    else             { src = wd; hi = dh; lo = dl; }
    float4 v = src[i];
    __nv_bfloat162 h0 = __floats2bfloat162_rn(v.x, v.y);
    __nv_bfloat162 h1 = __floats2bfloat162_rn(v.z, v.w);
    hi[i] = make_uint2(*(unsigned*)&h0, *(unsigned*)&h1);
    __nv_bfloat162 l0 = __floats2bfloat162_rn(v.x - __bfloat162float(h0.x),
                                              v.y - __bfloat162float(h0.y));
    __nv_bfloat162 l1 = __floats2bfloat162_rn(v.z - __bfloat162float(h1.x),
                                              v.w - __bfloat162float(h1.y));
    lo[i] = make_uint2(*(unsigned*)&l0, *(unsigned*)&l1);
}

// ---------------------------------------------------------------------------
// GEMM — EXACT round-10 config (empirical best ~290us/GEMM):
// 256 threads, block tile 128x128x32, warp tile 64x32, lb(256,2) -> 2 CTAs/SM,
// 3-stage cp.async pipeline (3 x 32KB = 96KB/CTA).
// ---------------------------------------------------------------------------
#define STG_BYTES 32768
#define NSTG 3
#define TG_SMEM (NSTG*STG_BYTES)     // 98304
#define SA_AH 0
#define SA_AL 8192
#define SA_BH 16384
#define SA_BL 24576

__device__ __forceinline__ unsigned swz_off(int r, int u) {
    return (unsigned)(r * 64 + ((u ^ ((r >> 1) & 3)) << 4));
}

__global__ __launch_bounds__(256, 2)
void gemm_tc2(const __nv_bfloat16* __restrict__ Ain_h, const __nv_bfloat16* __restrict__ Ain_l,
              const __nv_bfloat16* __restrict__ w0h, const __nv_bfloat16* __restrict__ w0l,
              const __nv_bfloat16* __restrict__ w1h, const __nv_bfloat16* __restrict__ w1l,
              const __nv_bfloat16* __restrict__ w2h, const __nv_bfloat16* __restrict__ w2l,
              __nv_bfloat16* __restrict__ d0h, __nv_bfloat16* __restrict__ d0l,
              __nv_bfloat16* __restrict__ d1h, __nv_bfloat16* __restrict__ d1l,
              __nv_bfloat16* __restrict__ d2h, __nv_bfloat16* __restrict__ d2l,
              float* __restrict__ Cout)
{
    extern __shared__ __align__(16) char smem[];
    const unsigned sb = smem_u32(smem);

    const int tid  = threadIdx.x;
    const int lane = tid & 31;
    const int wid  = tid >> 5;
    const int wm   = wid >> 2;        // 0..1  (64 M-rows each)
    const int wn   = wid & 3;         // 0..3  (32 N-cols each)
    const int g    = lane >> 2;
    const int tg   = lane & 3;
    const int bn   = blockIdx.x, bm = blockIdx.y, z = blockIdx.z;

    const __nv_bfloat16* Bh = (z == 0) ? w0h : (z == 1) ? w1h : w2h;
    const __nv_bfloat16* Bl = (z == 0) ? w0l : (z == 1) ? w1l : w2l;
    __nv_bfloat16* Dh = (z == 0) ? d0h : (z == 1) ? d1h : d2h;
    __nv_bfloat16* Dl = (z == 0) ? d0l : (z == 1) ? d1l : d2l;
    const int mode = Cout ? 0 : ((z <= 1) ? 2 : 1);

    const __nv_bfloat16* Ahg = Ain_h + (size_t)(bm * 128) * DMODEL;
    const __nv_bfloat16* Alg = Ain_l + (size_t)(bm * 128) * DMODEL;
    const __nv_bfloat16* Bhg = Bh + (size_t)(bn * 128) * DMODEL;
    const __nv_bfloat16* Blg = Bl + (size_t)(bn * 128) * DMODEL;
    const __nv_bfloat16* srcs[4] = {Ahg, Alg, Bhg, Blg};

    const int r_lo = tid >> 2;       // 0..63
    const int u_st = tid & 3;

    float acc[4][4][4];
#pragma unroll
    for (int mt = 0; mt < 4; mt++)
#pragma unroll
        for (int nt = 0; nt < 4; nt++)
#pragma unroll
            for (int e = 0; e < 4; e++) acc[mt][nt][e] = 0.f;

#define ISSUE_STAGE(S, BUF)                                                    \
    do {                                                                       \
        const int k0_ = (S) * 32;                                              \
        const unsigned stb_ = sb + (BUF) * STG_BYTES;                          \
        _Pragma("unroll")                                                      \
        for (int rep = 0; rep < 8; rep++) {                                    \
            const int arr = rep >> 1;                                          \
            const int r   = ((rep & 1) << 6) + r_lo;                           \
            cpa16(stb_ + arr * 8192 + swz_off(r, u_st),                        \
                  srcs[arr] + (size_t)r * DMODEL + k0_ + u_st * 8);            \
        }                                                                      \
    } while (0)

    // prologue: 2 stages in flight
    ISSUE_STAGE(0, 0); CPA_COMMIT();
    ISSUE_STAGE(1, 1); CPA_COMMIT();

    const int NST = DMODEL / 32;   // 64
    int buf = 0, nbuf = 2;
    for (int s = 0; s < NST; s++) {
        CPA_WAIT1();
        __syncthreads();
        if (s + 2 < NST) ISSUE_STAGE(s + 2, nbuf);
        CPA_COMMIT();

        const unsigned stb = sb + buf * STG_BYTES;
#pragma unroll
        for (int ks = 0; ks < 2; ks++) {
            const int u = 2 * ks + (lane >> 4);
            const int ar_base = wm * 64 + (lane & 15);
            const int br_base = wn * 32 + (lane & 15);
            unsigned afr[4][4], bfr[2][4];
            // A-hi, B-hi
#pragma unroll
            for (int mt = 0; mt < 4; mt++)
                ldsm4(afr[mt], stb + SA_AH + swz_off(ar_base + mt * 16, u));
#pragma unroll
            for (int bt = 0; bt < 2; bt++)
                ldsm4(bfr[bt], stb + SA_BH + swz_off(br_base + bt * 16, u));
            // P1: hh
#pragma unroll
            for (int mt = 0; mt < 4; mt++)
#pragma unroll
                for (int nt = 0; nt < 4; nt++)
                    mma16816(acc[mt][nt], afr[mt],
                             bfr[nt >> 1][nt & 1], bfr[nt >> 1][(nt & 1) + 2]);
            // B-lo; P2: h*l
#pragma unroll
            for (int bt = 0; bt < 2; bt++)
                ldsm4(bfr[bt], stb + SA_BL + swz_off(br_base + bt * 16, u));
#pragma unroll
            for (int mt = 0; mt < 4; mt++)
#pragma unroll
                for (int nt = 0; nt < 4; nt++)
                    mma16816(acc[mt][nt], afr[mt],
                             bfr[nt >> 1][nt & 1], bfr[nt >> 1][(nt & 1) + 2]);
            // A-lo, reload B-hi; P3: l*h
#pragma unroll
            for (int mt = 0; mt < 4; mt++)
                ldsm4(afr[mt], stb + SA_AL + swz_off(ar_base + mt * 16, u));
#pragma unroll
            for (int bt = 0; bt < 2; bt++)
                ldsm4(bfr[bt], stb + SA_BH + swz_off(br_base + bt * 16, u));
#pragma unroll
            for (int mt = 0; mt < 4; mt++)
#pragma unroll
                for (int nt = 0; nt < 4; nt++)
                    mma16816(acc[mt][nt], afr[mt],
                             bfr[nt >> 1][nt & 1], bfr[nt >> 1][(nt & 1) + 2]);
        }
        buf  = (buf  == 2) ? 0 : buf  + 1;
        nbuf = (nbuf == 2) ? 0 : nbuf + 1;
    }
#undef ISSUE_STAGE

    // ---- epilogue ----
#pragma unroll
    for (int mt = 0; mt < 4; mt++) {
#pragma unroll
        for (int nt = 0; nt < 4; nt++) {
            int m0  = bm * 128 + wm * 64 + mt * 16 + g;
            int col = wn * 32 + nt * 8 + tg * 2;
            float v00 = acc[mt][nt][0], v01 = acc[mt][nt][1];
            float v10 = acc[mt][nt][2], v11 = acc[mt][nt][3];
            if (mode == 0) {
                *(float2*)(Cout + (size_t)m0 * DMODEL + bn * 128 + col) = make_float2(v00, v01);
                *(float2*)(Cout + (size_t)(m0 + 8) * DMODEL + bn * 128 + col) = make_float2(v10, v11);
            } else {
                int b0 = m0 >> 11, s0 = m0 & 2047;
                int m1 = m0 + 8;
                int b1 = m1 >> 11, s1 = m1 & 2047;
                if (mode == 2) {
                    v00 *= rope_fac(s0, col); v01 *= rope_fac(s0, col + 1);
                    v10 *= rope_fac(s1, col); v11 *= rope_fac(s1, col + 1);
                }
                size_t i0 = ((size_t)(b0 * NH + bn) * SS + s0) * DH + col;
                size_t i1 = ((size_t)(b1 * NH + bn) * SS + s1) * DH + col;
                __nv_bfloat162 hb;
                hb = __floats2bfloat162_rn(v00, v01);
                *(unsigned*)(Dh + i0) = *(unsigned*)&hb;
                *(unsigned*)(Dl + i0) = packbf2(v00 - __bfloat162float(hb.x),
                                                v01 - __bfloat162float(hb.y));
                hb = __floats2bfloat162_rn(v10, v11);
                *(unsigned*)(Dh + i1) = *(unsigned*)&hb;
                *(unsigned*)(Dl + i1) = packbf2(v10 - __bfloat162float(hb.x),
                                                v11 - __bfloat162float(hb.y));
            }
        }
    }
}

// ---------------------------------------------------------------------------
// Causal flash attention (round-10 core) with PAIRED-QT load balancing:
// each CTA processes q-tiles (p, 15-p) sequentially -> constant 34 k-tiles
// per CTA; grid.x halves to 8.
// ---------------------------------------------------------------------------
#define AQH 0
#define AQL 32768
#define AKH 65536
#define AKL 81920
#define AVH 98304
#define AVL 114688
#define ATT_SMEM 131072

__global__ __launch_bounds__(256, 1)
void attn_mma_kernel(const __nv_bfloat16* __restrict__ Qh, const __nv_bfloat16* __restrict__ Ql,
                     const __nv_bfloat16* __restrict__ Kh, const __nv_bfloat16* __restrict__ Kl,
                     const __nv_bfloat16* __restrict__ Vh, const __nv_bfloat16* __restrict__ Vl,
                     __nv_bfloat16* __restrict__ Oh, __nv_bfloat16* __restrict__ Ol)
{
    extern __shared__ __align__(16) char smem[];
    const unsigned sbm = smem_u32(smem);

    const int tid  = threadIdx.x;
    const int lane = tid & 31;
    const int w    = tid >> 5;
    const int g    = lane >> 2;
    const int qd   = lane & 3;
    const int h    = blockIdx.y;
    const int b    = blockIdx.z;
    const int NQT  = SS / 128;                 // 16

    const size_t base = ((size_t)(b*NH + h)) * SS * DH;
    const __nv_bfloat16* Khg = Kh + base;
    const __nv_bfloat16* Klg = Kl + base;
    const __nv_bfloat16* Vhg = Vh + base;
    const __nv_bfloat16* Vlg = Vl + base;

    const float scale = 0.08838834764831845f;

    for (int qrep = 0; qrep < 2; qrep++) {
        const int qt = qrep == 0 ? (NQT - 1 - (int)blockIdx.x) : (int)blockIdx.x;

        __syncthreads();   // all warps done reading previous q-tile's Qs

        const __nv_bfloat16* Qhg = Qh + base + (size_t)qt * 128 * DH;
        const __nv_bfloat16* Qlg = Ql + base + (size_t)qt * 128 * DH;
#pragma unroll
        for (int rep = 0; rep < 8; rep++) {
            int idx = tid + rep * 256;
            int r = idx >> 4, u = idx & 15;
            unsigned off = (unsigned)(r * 256 + ((u ^ (r & 7)) << 4));
            *(uint4*)(smem + AQH + off) = *(const uint4*)(Qhg + (size_t)r * DH + u * 8);
            *(uint4*)(smem + AQL + off) = *(const uint4*)(Qlg + (size_t)r * DH + u * 8);
        }

        float o[16][4];
#pragma unroll
        for (int nj = 0; nj < 16; nj++)
#pragma unroll
            for (int e = 0; e < 4; e++) o[nj][e] = 0.f;
        float mrow[2] = {-INFINITY, -INFINITY};
        float lrow[2] = {0.f, 0.f};

        const int ktmax = 2 * qt + 1;

        for (int kt = 0; kt <= ktmax; kt++) {
            __syncthreads();
#pragma unroll
            for (int rep = 0; rep < 4; rep++) {
                int idx = tid + rep * 256;
                int r = idx >> 4, u = idx & 15;
                unsigned off = (unsigned)(r * 256 + ((u ^ (r & 7)) << 4));
                *(uint4*)(smem + AKH + off) = *(const uint4*)(Khg + (size_t)(kt*64 + r) * DH + u * 8);
                *(uint4*)(smem + AKL + off) = *(const uint4*)(Klg + (size_t)(kt*64 + r) * DH + u * 8);
            }
#pragma unroll
            for (int rep = 0; rep < 4; rep++) {
                int idx = tid + rep * 256;
                int kk = idx & 63, u = idx >> 6;
                uint4 hv = *(const uint4*)(Vhg + (size_t)(kt*64 + kk) * DH + u * 8);
                uint4 lv = *(const uint4*)(Vlg + (size_t)(kt*64 + kk) * DH + u * 8);
                const unsigned short* hs = (const unsigned short*)&hv;
                const unsigned short* ls = (const unsigned short*)&lv;
#pragma unroll
                for (int dd = 0; dd < 8; dd++) {
                    int d = u * 8 + dd;
                    unsigned off = (unsigned)(d * 128 + (((kk >> 3) ^ (d & 7)) << 4) + ((kk & 7) << 1));
                    *(unsigned short*)(smem + AVH + off) = hs[dd];
                    *(unsigned short*)(smem + AVL + off) = ls[dd];
                }
            }
            __syncthreads();

            float s[8][4];
#pragma unroll
            for (int nj = 0; nj < 8; nj++)
#pragma unroll
                for (int e = 0; e < 4; e++) s[nj][e] = 0.f;

#pragma unroll
            for (int ks = 0; ks < 8; ks++) {
                unsigned ah[4], al[4];
                {
                    int row = w * 16 + (lane & 15);
                    int u = 2 * ks + (lane >> 4);
                    unsigned off = (unsigned)(row * 256 + ((u ^ (row & 7)) << 4));
                    ldsm4(ah, sbm + AQH + off);
                    ldsm4(al, sbm + AQL + off);
                }
#pragma unroll
                for (int g4 = 0; g4 < 4; g4++) {
                    unsigned bh[4], bl[4];
                    int row = g4 * 16 + (lane & 15);
                    int u = 2 * ks + (lane >> 4);
                    unsigned off = (unsigned)(row * 256 + ((u ^ (row & 7)) << 4));
                    ldsm4(bh, sbm + AKH + off);
                    ldsm4(bl, sbm + AKL + off);
#pragma unroll
                    for (int jj = 0; jj < 2; jj++) {
                        int nj = 2 * g4 + jj;
                        mma16816(s[nj], ah, bh[jj], bh[jj + 2]);
                        mma16816(s[nj], ah, bl[jj], bl[jj + 2]);
                        mma16816(s[nj], al, bh[jj], bh[jj + 2]);
                    }
                }
            }

            const int r0 = qt * 128 + w * 16 + g;
            const int r1 = r0 + 8;
            const bool tail = (kt >= 2 * qt);
#pragma unroll
            for (int nj = 0; nj < 8; nj++) {
                int c0 = kt * 64 + nj * 8 + qd * 2;
#pragma unroll
                for (int e = 0; e < 4; e++) {
                    s[nj][e] *= scale;
                    if (tail) {
                        int col = c0 + (e & 1);
                        int row = (e < 2) ? r0 : r1;
                        if (col > row) s[nj][e] = -INFINITY;
                    }
                }
            }

            float alpha[2];
#pragma unroll
            for (int half = 0; half < 2; half++) {
                float mx = -INFINITY;
#pragma unroll
                for (int nj = 0; nj < 8; nj++)
                    mx = fmaxf(mx, fmaxf(s[nj][2*half], s[nj][2*half+1]));
                mx = fmaxf(mx, __shfl_xor_sync(0xffffffffu, mx, 1));
                mx = fmaxf(mx, __shfl_xor_sync(0xffffffffu, mx, 2));
                float newm = fmaxf(mrow[half], mx);
                float sum = 0.f;
#pragma unroll
                for (int nj = 0; nj < 8; nj++) {
                    float p0 = __expf(s[nj][2*half]   - newm);
                    float p1 = __expf(s[nj][2*half+1] - newm);
                    s[nj][2*half]   = p0;
                    s[nj][2*half+1] = p1;
                    sum += p0 + p1;
                }
                sum += __shfl_xor_sync(0xffffffffu, sum, 1);
                sum += __shfl_xor_sync(0xffffffffu, sum, 2);
                alpha[half] = __expf(mrow[half] - newm);
                lrow[half] = lrow[half] * alpha[half] + sum;
                mrow[half] = newm;
            }
#pragma unroll
            for (int nj = 0; nj < 16; nj++) {
                o[nj][0] *= alpha[0]; o[nj][1] *= alpha[0];
                o[nj][2] *= alpha[1]; o[nj][3] *= alpha[1];
            }

#pragma unroll
            for (int tpv = 0; tpv < 4; tpv++) {
                unsigned pah[4], pal[4];
                {
                    float p00 = s[2*tpv][0],   p01 = s[2*tpv][1];
                    float p02 = s[2*tpv][2],   p03 = s[2*tpv][3];
                    float p10 = s[2*tpv+1][0], p11 = s[2*tpv+1][1];
                    float p12 = s[2*tpv+1][2], p13 = s[2*tpv+1][3];
                    __nv_bfloat162 hb;
                    hb = __floats2bfloat162_rn(p00, p01); pah[0] = *(unsigned*)&hb;
                    pal[0] = packbf2(p00 - __bfloat162float(hb.x), p01 - __bfloat162float(hb.y));
                    hb = __floats2bfloat162_rn(p02, p03); pah[1] = *(unsigned*)&hb;
                    pal[1] = packbf2(p02 - __bfloat162float(hb.x), p03 - __bfloat162float(hb.y));
                    hb = __floats2bfloat162_rn(p10, p11); pah[2] = *(unsigned*)&hb;
                    pal[2] = packbf2(p10 - __bfloat162float(hb.x), p11 - __bfloat162float(hb.y));
                    hb = __floats2bfloat162_rn(p12, p13); pah[3] = *(unsigned*)&hb;
                    pal[3] = packbf2(p12 - __bfloat162float(hb.x), p13 - __bfloat162float(hb.y));
                }
#pragma unroll
                for (int g4 = 0; g4 < 8; g4++) {
                    unsigned vbh[4], vbl[4];
                    int row = g4 * 16 + (lane & 15);
                    int u = 2 * tpv + (lane >> 4);
                    unsigned off = (unsigned)(row * 128 + ((u ^ (row & 7)) << 4));
                    ldsm4(vbh, sbm + AVH + off);
                    ldsm4(vbl, sbm + AVL + off);
#pragma unroll
                    for (int jj = 0; jj < 2; jj++) {
                        int njo = 2 * g4 + jj;
                        mma16816(o[njo], pah, vbh[jj], vbh[jj + 2]);
                        mma16816(o[njo], pah, vbl[jj], vbl[jj + 2]);
                        mma16816(o[njo], pal, vbh[jj], vbh[jj + 2]);
                    }
                }
            }
        }

        // ---- normalize + write bf16 hi/lo [B,S,D] ----
        const float inv0 = 1.f / lrow[0];
        const float inv1 = 1.f / lrow[1];
        const int r0 = qt * 128 + w * 16 + g;
        const int r1 = r0 + 8;
        __nv_bfloat16* Ohg = Oh + (size_t)b * SS * DMODEL + (size_t)h * DH;
        __nv_bfloat16* Olg = Ol + (size_t)b * SS * DMODEL + (size_t)h * DH;
#pragma unroll
        for (int njo = 0; njo < 16; njo++) {
            int col = njo * 8 + qd * 2;
            float v0 = o[njo][0] * inv0, v1 = o[njo][1] * inv0;
            float v2 = o[njo][2] * inv1, v3 = o[njo][3] * inv1;
            __nv_bfloat162 hb;
            hb = __floats2bfloat162_rn(v0, v1);
            *(unsigned*)(Ohg + (size_t)r0 * DMODEL + col) = *(unsigned*)&hb;
            *(unsigned*)(Olg + (size_t)r0 * DMODEL + col) =
                packbf2(v0 - __bfloat162float(hb.x), v1 - __bfloat162float(hb.y));
            hb = __floats2bfloat162_rn(v2, v3);
            *(unsigned*)(Ohg + (size_t)r1 * DMODEL + col) = *(unsigned*)&hb;
            *(unsigned*)(Olg + (size_t)r1 * DMODEL + col) =
                packbf2(v2 - __bfloat162float(hb.x), v3 - __bfloat162float(hb.y));
        }
    }
}

// ---------------------------------------------------------------------------
// Launch
// ---------------------------------------------------------------------------
extern "C" void kernel_launch(void* const* d_in, const int* in_sizes, int n_in,
                              void* d_out, int out_size)
{
    (void)out_size;
    const int X_ELEMS = MTOT * DMODEL;

    const float *x, *Wq, *Wk, *Wv, *Wd;
    if (n_in >= 6 && in_sizes[0] == X_ELEMS) {
        x  = (const float*)d_in[0];
        Wq = (const float*)d_in[2];
        Wk = (const float*)d_in[3];
        Wv = (const float*)d_in[4];
        Wd = (const float*)d_in[5];
    } else {
        Wd = (const float*)d_in[0];
        Wk = (const float*)d_in[1];
        Wq = (const float*)d_in[2];
        Wv = (const float*)d_in[3];
        x  = (const float*)d_in[5];
    }
    float* out = (float*)d_out;

    __nv_bfloat16 *xh,*xl,*wqh,*wql,*wkh,*wkl,*wvh,*wvl,*wdh,*wdl;
    __nv_bfloat16 *Qh,*Ql,*Kh,*Kl,*Vh,*Vl,*Oh,*Ol;
    cudaGetSymbolAddress((void**)&xh,  g_xh);  cudaGetSymbolAddress((void**)&xl,  g_xl);
    cudaGetSymbolAddress((void**)&wqh, g_wqh); cudaGetSymbolAddress((void**)&wql, g_wql);
    cudaGetSymbolAddress((void**)&wkh, g_wkh); cudaGetSymbolAddress((void**)&wkl, g_wkl);
    cudaGetSymbolAddress((void**)&wvh, g_wvh); cudaGetSymbolAddress((void**)&wvl, g_wvl);
    cudaGetSymbolAddress((void**)&wdh, g_wdh); cudaGetSymbolAddress((void**)&wdl, g_wdl);
    cudaGetSymbolAddress((void**)&Qh,  g_Qh);  cudaGetSymbolAddress((void**)&Ql,  g_Ql);
    cudaGetSymbolAddress((void**)&Kh,  g_Kh);  cudaGetSymbolAddress((void**)&Kl,  g_Kl);
    cudaGetSymbolAddress((void**)&Vh,  g_Vh);  cudaGetSymbolAddress((void**)&Vl,  g_Vl);
    cudaGetSymbolAddress((void**)&Oh,  g_Oh);  cudaGetSymbolAddress((void**)&Ol,  g_Ol);

    const int WN4 = DMODEL * DMODEL / 4;
    split6_kernel<<<dim3(WN4/256, 6), 256>>>(
        (const float4*)x, (const float4*)Wq, (const float4*)Wk,
        (const float4*)Wv, (const float4*)Wd,
        (uint2*)xh, (uint2*)xl, (uint2*)wqh, (uint2*)wql,
        (uint2*)wkh, (uint2*)wkl, (uint2*)wvh, (uint2*)wvl,
        (uint2*)wdh, (uint2*)wdl);

    cudaFuncSetAttribute(gemm_tc2,
                         cudaFuncAttributeMaxDynamicSharedMemorySize, TG_SMEM);
    cudaFuncSetAttribute(attn_mma_kernel,
                         cudaFuncAttributeMaxDynamicSharedMemorySize, ATT_SMEM);

    // fused Q/K/V projection (+RoPE on Q,K)
    gemm_tc2<<<dim3(DMODEL/128, MTOT/128, 3), 256, TG_SMEM>>>(
        xh, xl,
        wqh, wql, wkh, wkl, wvh, wvl,
        Qh, Ql, Kh, Kl, Vh, Vl,
        nullptr);

    // paired-qt attention: grid.x = 8 (each CTA does q-tiles p and 15-p)
    attn_mma_kernel<<<dim3(SS/256, NH, BB), 256, ATT_SMEM>>>(Qh, Ql, Kh, Kl, Vh, Vl, Oh, Ol);

    // output projection -> fp32 out
    gemm_tc2<<<dim3(DMODEL/128, MTOT/128, 1), 256, TG_SMEM>>>(
        Oh, Ol,
        wdh, wdl, wdh, wdl, wdh, wdl,
        nullptr, nullptr, nullptr, nullptr, nullptr, nullptr,
        out);
}